// round 17
// baseline (speedup 1.0000x reference)
#include <cuda_runtime.h>
#include <cuda_fp16.h>
#include <math.h>
#include <stdint.h>

#define BB 32
#define TT 4096
#define DD 512
#define UU 256

#define APF 520    // full A tile pitch in halves (512 k + 8 pad); row phase 4r mod 32
#define BPH2 264   // Bs pitch in halves (256 u + 8 pad)

// smem offsets (bytes)
#define OFF_AS   0                       // [128][APF] halves = 133120
#define OFF_BS   133120                  // 2 x [32][BPH2] halves = 33792
#define OFF_SRED 166912                  // 128 floats = 512
#define OFF_SM4  167424                  // 512 float4 = 8192
#define OFF_SH   175616                  // 256 floats = 1024
#define OFF_SV   176640                  // 256 floats = 1024
#define SMEM_SZ  177664

// scratch (no allocations allowed)
__device__ float  g_hq16[BB * 16 * UU]; // 16 d-chunk partials of hq
__device__ float  g_scores[BB * TT];    // exp(score)
__device__ float  g_sum[BB];            // per-batch sum of exp
__device__ float  g_ctx_raw[BB * DD];   // unnormalized context
__device__ int    g_done[BB];           // per-batch CTA completion counter
__device__ __half g_W1c[DD * UU];       // W1 fp16, native [k][u]

__device__ __forceinline__ uint32_t smem_u32(const void* p) {
    uint32_t a;
    asm("{ .reg .u64 t; cvta.to.shared.u64 t, %1; cvt.u32.u64 %0, t; }"
        : "=r"(a) : "l"(p));
    return a;
}
__device__ __forceinline__ void cp_async16(uint32_t dst, const void* src) {
    asm volatile("cp.async.cg.shared.global [%0], [%1], 16;"
                 :: "r"(dst), "l"(src) : "memory");
}
__device__ __forceinline__ void cp_commit() {
    asm volatile("cp.async.commit_group;" ::: "memory");
}
__device__ __forceinline__ void cp_wait0() {
    asm volatile("cp.async.wait_group 0;" ::: "memory");
}
__device__ __forceinline__ void mma_f16(float c[4], const uint32_t a[4],
                                        const uint32_t b[2]) {
    asm volatile(
        "mma.sync.aligned.m16n8k16.row.col.f32.f16.f16.f32 "
        "{%0,%1,%2,%3}, {%4,%5,%6,%7}, {%8,%9}, {%0,%1,%2,%3};"
        : "+f"(c[0]), "+f"(c[1]), "+f"(c[2]), "+f"(c[3])
        : "r"(a[0]), "r"(a[1]), "r"(a[2]), "r"(a[3]), "r"(b[0]), "r"(b[1]));
}
__device__ __forceinline__ void ldsm_x4(uint32_t r[4], uint32_t addr) {
    asm volatile("ldmatrix.sync.aligned.m8n8.x4.shared.b16 {%0,%1,%2,%3}, [%4];"
                 : "=r"(r[0]), "=r"(r[1]), "=r"(r[2]), "=r"(r[3]) : "r"(addr));
}
__device__ __forceinline__ void ldsm_x4_t(uint32_t r[4], uint32_t addr) {
    asm volatile("ldmatrix.sync.aligned.m8n8.x4.trans.shared.b16 {%0,%1,%2,%3}, [%4];"
                 : "=r"(r[0]), "=r"(r[1]), "=r"(r[2]), "=r"(r[3]) : "r"(addr));
}
__device__ __forceinline__ float tanh_fast(float x) {
    const float e = __expf(2.f * x);
    return 1.f - __fdividef(2.f, e + 1.f);
}

// ---------------------------------------------------------------------------
// prep: blocks 0..127 -> W1 fp32->fp16 convert; blocks 128..639 -> hq partials
// (b = (blk-128)>>4, d-chunk = &15, d=32); chunk 0 zeroes sums/counters.
// ---------------------------------------------------------------------------
__global__ void prep_kernel(const float* __restrict__ W1,
                            const float* __restrict__ query,
                            const float* __restrict__ W2,
                            const float* __restrict__ b1,
                            const float* __restrict__ b2) {
    __shared__ float q[32];
    const int blk = blockIdx.x;
    const int tid = threadIdx.x;
    if (blk < 128) {
        const int idx = blk * 1024 + tid * 4;
        const float4 v = *(const float4*)(W1 + idx);
        __half2 a = __floats2half2_rn(v.x, v.y);
        __half2 c = __floats2half2_rn(v.z, v.w);
        *(uint2*)(g_W1c + idx) = make_uint2(*(uint32_t*)&a, *(uint32_t*)&c);
    } else {
        const int cidx  = blk - 128;
        const int b     = cidx >> 4;
        const int chunk = cidx & 15;
        const int d0    = chunk * 32;
        const int u     = tid;
        if (chunk == 0) {
            if (u == 0) { g_sum[b] = 0.f; g_done[b] = 0; }
            g_ctx_raw[b * DD + u] = 0.f;
            g_ctx_raw[b * DD + 256 + u] = 0.f;
        }
        if (tid < 32) q[tid] = query[b * DD + d0 + tid];
        __syncthreads();
        float acc = (chunk == 0) ? (b1[u] + b2[u]) : 0.f;
#pragma unroll 16
        for (int d = 0; d < 32; ++d)
            acc = fmaf(q[d], W2[(size_t)(d0 + d) * UU + u], acc);
        g_hq16[cidx * UU + u] = acc;
    }
}

// ---------------------------------------------------------------------------
// scores + fused context + last-CTA finalize:
// fp16 mma.m16n8k16, 128t x 256u x 512k per CTA, 512 thr (2M x 8N).
// Full A tile in smem (fp16); B double-buffered via cp.async. Epilogue:
// tanh dot V, exp, per-batch sum, unnormalized ctx from SMEM A, then the
// last CTA per batch normalizes ctx and writes all the batch's weights.
// ---------------------------------------------------------------------------
__global__ __launch_bounds__(512, 1)
void scores_mma(const float* __restrict__ values,
                const float* __restrict__ Vv,
                float* __restrict__ ctx,
                float* __restrict__ wout) {
    extern __shared__ char smc[];
    __half* As   = (__half*)(smc + OFF_AS);
    __half* Bs   = (__half*)(smc + OFF_BS);
    float*  sred = (float*)(smc + OFF_SRED);
    float4* sm4  = (float4*)(smc + OFF_SM4);
    float*  sh   = (float*)(smc + OFF_SH);
    float*  sv   = (float*)(smc + OFF_SV);
    __shared__ int is_last;
    const uint32_t As_u32 = smem_u32(As);
    const uint32_t Bs_u32 = smem_u32(Bs);

    const int b     = blockIdx.y;
    const int tbase = blockIdx.x * 128;
    const int tid   = threadIdx.x;
    const int lane  = tid & 31;
    const int wid   = tid >> 5;
    const int wm    = wid & 1;
    const int wn    = wid >> 1;
    const int g     = lane >> 2;
    const int tg    = lane & 3;

    const int lrow = lane & 15;
    const int lk8  = (lane & 16) >> 1;

    const float* vbase = values + ((size_t)b * TT + tbase) * DD;

    const int at0 = tid >> 3;
    const int k4a = tid & 7;
    const int bk = tid >> 4;
    const int bu = (tid & 15) * 16;

    // stage hq (pre-reduced) + V into smem; consumed in epilogue
    if (tid < 256) {
        const float* hqb = g_hq16 + (size_t)b * 16 * UU + tid;
        float h = 0.f;
#pragma unroll
        for (int j = 0; j < 16; ++j) h += hqb[j * UU];
        sh[tid] = h;
        sv[tid] = Vv[tid];
    }

    float acc[4][4][4];
#pragma unroll
    for (int i = 0; i < 4; ++i)
#pragma unroll
        for (int j = 0; j < 4; ++j)
#pragma unroll
            for (int c = 0; c < 4; ++c) acc[i][j][c] = 0.f;

    float4 pfA0, pfA1;

    // ---- prologue: stage chunk 0 ----
    {
        const __half* w1p = g_W1c + (size_t)bk * UU + bu;
        const uint32_t bdst = Bs_u32 + (bk * BPH2 + bu) * 2;
        cp_async16(bdst, w1p);
        cp_async16(bdst + 16, w1p + 8);
        cp_commit();
        pfA0 = *(const float4*)(vbase + (size_t)at0 * DD + k4a * 4);
        pfA1 = *(const float4*)(vbase + (size_t)(at0 + 64) * DD + k4a * 4);
        __half2 p0 = __floats2half2_rn(pfA0.x, pfA0.y);
        __half2 p1 = __floats2half2_rn(pfA0.z, pfA0.w);
        __half2 p2 = __floats2half2_rn(pfA1.x, pfA1.y);
        __half2 p3 = __floats2half2_rn(pfA1.z, pfA1.w);
        *(uint2*)(As + at0 * APF + k4a * 4) =
            make_uint2(*(uint32_t*)&p0, *(uint32_t*)&p1);
        *(uint2*)(As + (at0 + 64) * APF + k4a * 4) =
            make_uint2(*(uint32_t*)&p2, *(uint32_t*)&p3);
        cp_wait0();
    }
    __syncthreads();

    for (int c = 0; c < 16; ++c) {
        const int buf = c & 1;
        const int nxt = buf ^ 1;
        const int k0  = c * 32;

        if (c < 15) {
            const int k0n = k0 + 32;
            const __half* w1p = g_W1c + (size_t)(k0n + bk) * UU + bu;
            const uint32_t bdst = Bs_u32 + (nxt * 32 * BPH2 + bk * BPH2 + bu) * 2;
            cp_async16(bdst, w1p);
            cp_async16(bdst + 16, w1p + 8);
            cp_commit();
            pfA0 = *(const float4*)(vbase + (size_t)at0 * DD + k0n + k4a * 4);
            pfA1 = *(const float4*)(vbase + (size_t)(at0 + 64) * DD + k0n + k4a * 4);
        }

        const uint32_t Bbase = Bs_u32 + buf * 32 * BPH2 * 2;
#pragma unroll
        for (int ks = 0; ks < 2; ++ks) {
            const int kk = k0 + ks * 16;
            uint32_t a[4][4];
#pragma unroll
            for (int mi = 0; mi < 4; ++mi) {
                const int row = wm * 64 + mi * 16 + lrow;
                ldsm_x4(a[mi], As_u32 + (row * APF + kk + lk8) * 2);
            }
            uint32_t bf[4][2];
#pragma unroll
            for (int j = 0; j < 2; ++j) {
                uint32_t r[4];
                const int uj = wn * 32 + j * 16;
                ldsm_x4_t(r, Bbase + ((ks * 16 + lrow) * BPH2 + uj + lk8) * 2);
                bf[2 * j][0]     = r[0];
                bf[2 * j][1]     = r[1];
                bf[2 * j + 1][0] = r[2];
                bf[2 * j + 1][1] = r[3];
            }
#pragma unroll
            for (int mi = 0; mi < 4; ++mi)
#pragma unroll
                for (int nj = 0; nj < 4; ++nj)
                    mma_f16(acc[mi][nj], a[mi], bf[nj]);
        }

        if (c < 15) {
            const int k0n = k0 + 32;
            __half2 p0 = __floats2half2_rn(pfA0.x, pfA0.y);
            __half2 p1 = __floats2half2_rn(pfA0.z, pfA0.w);
            __half2 p2 = __floats2half2_rn(pfA1.x, pfA1.y);
            __half2 p3 = __floats2half2_rn(pfA1.z, pfA1.w);
            *(uint2*)(As + at0 * APF + k0n + k4a * 4) =
                make_uint2(*(uint32_t*)&p0, *(uint32_t*)&p1);
            *(uint2*)(As + (at0 + 64) * APF + k0n + k4a * 4) =
                make_uint2(*(uint32_t*)&p2, *(uint32_t*)&p3);
            cp_wait0();
            __syncthreads();
        }
    }

    // ---- epilogue: tanh dot V, exp, per-batch sum ----
    float sp[4][2];
#pragma unroll
    for (int mi = 0; mi < 4; ++mi) { sp[mi][0] = 0.f; sp[mi][1] = 0.f; }

#pragma unroll
    for (int nj = 0; nj < 4; ++nj) {
        const int u0  = wn * 32 + nj * 8 + 2 * tg;
        const float h0 = sh[u0];
        const float h1 = sh[u0 + 1];
        const float v0 = sv[u0];
        const float v1 = sv[u0 + 1];
#pragma unroll
        for (int mi = 0; mi < 4; ++mi) {
            sp[mi][0] = fmaf(tanh_fast(acc[mi][nj][0] + h0), v0, sp[mi][0]);
            sp[mi][0] = fmaf(tanh_fast(acc[mi][nj][1] + h1), v1, sp[mi][0]);
            sp[mi][1] = fmaf(tanh_fast(acc[mi][nj][2] + h0), v0, sp[mi][1]);
            sp[mi][1] = fmaf(tanh_fast(acc[mi][nj][3] + h1), v1, sp[mi][1]);
        }
    }
#pragma unroll
    for (int off = 1; off <= 2; off <<= 1)
#pragma unroll
        for (int mi = 0; mi < 4; ++mi) {
            sp[mi][0] += __shfl_xor_sync(0xffffffffu, sp[mi][0], off);
            sp[mi][1] += __shfl_xor_sync(0xffffffffu, sp[mi][1], off);
        }

    if (tid < 128) sred[tid] = 0.f;
    __syncthreads();
    if (tg == 0) {
#pragma unroll
        for (int mi = 0; mi < 4; ++mi) {
            atomicAdd(&sred[wm * 64 + mi * 16 + g],     sp[mi][0]);
            atomicAdd(&sred[wm * 64 + mi * 16 + g + 8], sp[mi][1]);
        }
    }
    __syncthreads();
    if (tid < 128) {
        const float e = __expf(sred[tid]);   // |score| <= sum|V_u| ~ 13: safe
        g_scores[(size_t)b * TT + tbase + tid] = e;
        float ws = e;
#pragma unroll
        for (int off = 16; off; off >>= 1)
            ws += __shfl_down_sync(0xffffffffu, ws, off);
        if (lane == 0) atomicAdd(&g_sum[b], ws);
        sred[tid] = e;
    }
    __syncthreads();

    // ---- fused ctx from SMEM A tile (fp16): ctx_raw += sum_t e_t * v[t,:] ----
    if (ctx) {
        const int d4  = tid & 127;
        const int grp = tid >> 7;
        float4 a4 = make_float4(0.f, 0.f, 0.f, 0.f);
#pragma unroll 8
        for (int tt = grp; tt < 128; tt += 4) {
            const float wv = sred[tt];
            const uint2 hv = *(const uint2*)(As + tt * APF + d4 * 4);
            const float2 f01 = __half22float2(*(const __half2*)&hv.x);
            const float2 f23 = __half22float2(*(const __half2*)&hv.y);
            a4.x = fmaf(wv, f01.x, a4.x);
            a4.y = fmaf(wv, f01.y, a4.y);
            a4.z = fmaf(wv, f23.x, a4.z);
            a4.w = fmaf(wv, f23.y, a4.w);
        }
        sm4[grp * 128 + d4] = a4;
        __syncthreads();
        if (grp == 0) {
            const float4 a1 = sm4[128 + d4], a2 = sm4[256 + d4], a3 = sm4[384 + d4];
            a4.x += a1.x + a2.x + a3.x;
            a4.y += a1.y + a2.y + a3.y;
            a4.z += a1.z + a2.z + a3.z;
            a4.w += a1.w + a2.w + a3.w;
            float* o = g_ctx_raw + b * DD + d4 * 4;
            atomicAdd(o + 0, a4.x);
            atomicAdd(o + 1, a4.y);
            atomicAdd(o + 2, a4.z);
            atomicAdd(o + 3, a4.w);
        }
    }

    // ---- last CTA per batch finalizes: ctx/wout = raw / sum ----
    __syncthreads();
    if (tid == 0) {
        __threadfence();                         // release our writes
        is_last = (atomicAdd(&g_done[b], 1) == BB - 1);
    }
    __syncthreads();
    if (is_last) {
        __threadfence();                         // acquire peers' writes
        const float inv = __fdividef(1.f, g_sum[b]);
        if (ctx && tid < 128) {
            float4 v = *(const float4*)(g_ctx_raw + b * DD + tid * 4);
            v.x *= inv; v.y *= inv; v.z *= inv; v.w *= inv;
            *(float4*)(ctx + b * DD + tid * 4) = v;
        }
        if (wout) {
            for (int i = tid; i < TT; i += 512)
                wout[(size_t)b * TT + i] = g_scores[(size_t)b * TT + i] * inv;
        }
    }
}

// ---------------------------------------------------------------------------
extern "C" void kernel_launch(void* const* d_in, const int* in_sizes, int n_in,
                              void* d_out, int out_size) {
    const float* values = (const float*)d_in[0];
    const float* query  = (const float*)d_in[1];
    const float* W1     = (const float*)d_in[2];
    const float* b1     = (const float*)d_in[3];
    const float* W2     = (const float*)d_in[4];
    const float* b2     = (const float*)d_in[5];
    const float* Vv     = (const float*)d_in[6];
    // d_in[7] = bV: constant logit shift, cancels exactly in softmax.

    float* out  = (float*)d_out;
    float* ctx  = nullptr;
    float* wout = nullptr;
    if (out_size >= BB * DD + BB * TT) {
        ctx  = out;
        wout = out + BB * DD;
    } else if (out_size == BB * TT) {
        wout = out;
    } else {
        ctx = out;
    }

    cudaFuncSetAttribute(scores_mma, cudaFuncAttributeMaxDynamicSharedMemorySize,
                         SMEM_SZ);

    prep_kernel<<<640, 256>>>(W1, query, W2, b1, b2);
    scores_mma<<<dim3(TT / 128, BB), 512, SMEM_SZ>>>(values, Vv, ctx, wout);
}